// round 16
// baseline (speedup 1.0000x reference)
#include <cuda_runtime.h>
#include <cuda_fp16.h>
#include <cstdint>

#define DI __device__ __forceinline__

DI unsigned f2t(float x) { unsigned u; asm("cvt.rna.tf32.f32 %0, %1;" : "=r"(u) : "f"(x)); return u; }

DI void mma8(float c[4], const unsigned a[4], const unsigned b[2]) {
    asm("mma.sync.aligned.m16n8k8.row.col.f32.tf32.tf32.f32 "
        "{%0,%1,%2,%3}, {%4,%5,%6,%7}, {%8,%9}, {%0,%1,%2,%3};"
        : "+f"(c[0]), "+f"(c[1]), "+f"(c[2]), "+f"(c[3])
        : "r"(a[0]), "r"(a[1]), "r"(a[2]), "r"(a[3]), "r"(b[0]), "r"(b[1]));
}

DI void mma16h(float c[4], const unsigned a[4], const unsigned b[2]) {
    asm("mma.sync.aligned.m16n8k16.row.col.f32.f16.f16.f32 "
        "{%0,%1,%2,%3}, {%4,%5,%6,%7}, {%8,%9}, {%0,%1,%2,%3};"
        : "+f"(c[0]), "+f"(c[1]), "+f"(c[2]), "+f"(c[3])
        : "r"(a[0]), "r"(a[1]), "r"(a[2]), "r"(a[3]), "r"(b[0]), "r"(b[1]));
}

DI unsigned packh2(float lo, float hi) {
    __half2 h = __floats2half2_rn(lo, hi);
    return *(unsigned*)&h;
}

DI uint32_t smem_u32(const void* p) {
    uint32_t a;
    asm("{ .reg .u64 t; cvta.to.shared.u64 t, %1; cvt.u32.u64 %0, t; }" : "=r"(a) : "l"(p));
    return a;
}

DI void cp_async16(uint32_t dst, const void* src) {
    asm volatile("cp.async.ca.shared.global [%0], [%1], 16;" :: "r"(dst), "l"(src) : "memory");
}
#define CP_COMMIT() asm volatile("cp.async.commit_group;" ::: "memory")
#define CP_WAIT0()  asm volatile("cp.async.wait_group 0;" ::: "memory")

// ---- scratch (device globals; no allocations allowed) ----
#define KC 8
__device__ float  g_fc1[2][4096 * 256];
__device__ float  g_h  [2][4096 * 64];
__device__ __half g_hth[2 * 64 * 4096];
__device__ __half g_aggp[2][KC][4096 * 64];
__device__ int    g_degp[2][KC][4096];
__device__ float  g_part[4096];
__device__ __half g_w1h[2 * 256 * 4096];

// ============================================================================
// Pre-pass: w1 -> RNE fp16.
// ============================================================================
__global__ void cvt_w1h(const float* __restrict__ w0, const float* __restrict__ w1,
                        __half* __restrict__ out)
{
    int idx = blockIdx.x * blockDim.x + threadIdx.x;
    int z = idx >= 262144;
    int li = idx - z * 262144;
    float4 v = ((const float4*)(z ? w1 : w0))[li];
    uint2 u;
    u.x = packh2(v.x, v.y);
    u.y = packh2(v.z, v.w);
    ((uint2*)out)[idx] = u;
}

// ============================================================================
// fc1 via FP16 HMMA, BK=64, BM=64 x BN=256; B via cp.async (raw halves),
// registers cut for 2 CTAs/SM.  grid (mt=64, z=2) = 128 CTAs.
// ============================================================================
#define LDH 36
#define ASH(s, r, c) hsm[(s) * (64 * LDH) + (r) * LDH + (c)]
#define BSH(s, r, c) hsm[2 * 64 * LDH + (s) * (256 * LDH) + (r) * LDH + (c)]

__global__ void __launch_bounds__(256, 2)
fc1_h(const float* __restrict__ A0, const float* __restrict__ A1,
      const __half* __restrict__ Bh,
      const float* __restrict__ bias0, const float* __restrict__ bias1,
      float* __restrict__ C)
{
    extern __shared__ unsigned hsm[];
    constexpr int K = 4096, BK = 64;
    const int tid = threadIdx.x, warp = tid >> 5, lane = tid & 31;
    const int wm = warp & 1, wn = warp >> 1;          // 2 m-warps x 4 n-warps
    const int gid = lane >> 2, tig = lane & 3;
    const int z = blockIdx.y;
    const size_t m0 = (size_t)blockIdx.x * 64;
    const int ax = tid & 15, ay = tid >> 4;           // A: 16 float4/row, 16 rows/pass
    const int bx = tid & 7,  by = tid >> 3;           // B: 8 x 16B/row, 32 rows/pass

    const float*  A = (z ? A1 : A0) + (m0 + ay) * (size_t)K + ax * 4;
    const __half* B = Bh + (size_t)z * 256 * 4096 + (size_t)by * K + bx * 8;
    const float* bias = z ? bias1 : bias0;
    float* Cb = C + (size_t)z * 4096 * 256;

    const uint32_t bsm = smem_u32(hsm) + (2 * 64 * LDH) * 4;

    float acc[2][8][4];
#pragma unroll
    for (int i = 0; i < 2; i++)
#pragma unroll
        for (int j = 0; j < 8; j++)
#pragma unroll
            for (int e = 0; e < 4; e++) acc[i][j][e] = 0.f;

    float4 ra[4];
    const int nIter = K / BK;                          // 64

    auto ldA = [&](int it) {
        const size_t ko = (size_t)it * BK;
#pragma unroll
        for (int p = 0; p < 4; p++)
            ra[p] = *(const float4*)(A + (size_t)p * 16 * K + ko);
    };
    auto stA = [&](int s) {
#pragma unroll
        for (int p = 0; p < 4; p++) {
            uint2 t;
            t.x = packh2(ra[p].x, ra[p].y);
            t.y = packh2(ra[p].z, ra[p].w);
            *(uint2*)&ASH(s, p * 16 + ay, ax * 2) = t;
        }
    };
    auto cpB = [&](int it) {
        const size_t ko = (size_t)it * BK;
        const int s = it & 1;
#pragma unroll
        for (int p = 0; p < 8; p++) {
            uint32_t dst = bsm + (uint32_t)(s * 256 * LDH + (p * 32 + by) * LDH + bx * 4) * 4;
            cp_async16(dst, B + (size_t)p * 32 * K + ko);
        }
    };

    ldA(0);
    cpB(0); CP_COMMIT();
    stA(0);
    ldA(1);
    CP_WAIT0();
    __syncthreads();

    for (int it = 0; it < nIter; it++) {
        const int cur = it & 1;
        if (it + 1 < nIter) { cpB(it + 1); CP_COMMIT(); stA(cur ^ 1); }
        if (it + 2 < nIter) ldA(it + 2);
#pragma unroll
        for (int ks = 0; ks < BK / 16; ks++) {
            unsigned af[2][4], bf[8][2];
#pragma unroll
            for (int mt = 0; mt < 2; mt++) {
                int rr = wm * 32 + mt * 16 + gid;
                af[mt][0] = ASH(cur, rr,     ks * 8 + tig);
                af[mt][1] = ASH(cur, rr + 8, ks * 8 + tig);
                af[mt][2] = ASH(cur, rr,     ks * 8 + tig + 4);
                af[mt][3] = ASH(cur, rr + 8, ks * 8 + tig + 4);
            }
#pragma unroll
            for (int nt = 0; nt < 8; nt++) {
                int cc = wn * 64 + nt * 8 + gid;
                bf[nt][0] = BSH(cur, cc, ks * 8 + tig);
                bf[nt][1] = BSH(cur, cc, ks * 8 + tig + 4);
            }
#pragma unroll
            for (int mt = 0; mt < 2; mt++)
#pragma unroll
                for (int nt = 0; nt < 8; nt++)
                    mma16h(acc[mt][nt], af[mt], bf[nt]);
        }
        CP_WAIT0();
        __syncthreads();
    }

#pragma unroll
    for (int mt = 0; mt < 2; mt++)
#pragma unroll
        for (int nt = 0; nt < 8; nt++) {
            size_t row = m0 + wm * 32 + mt * 16 + gid;
            size_t col = wn * 64 + nt * 8 + tig * 2;
#pragma unroll
            for (int e = 0; e < 4; e++) {
                size_t r = row + (size_t)(e >> 1) * 8;
                size_t c = col + (size_t)(e & 1);
                Cb[r * 256 + c] = acc[mt][nt][e] + bias[c];
            }
        }
}

// ============================================================================
// FUSED fc2+fc3 (+relu, +fp16 transpose) — R14 config, unchanged.
// ============================================================================
#define P1LD 68
#define P2LD 132
#define AS1(s, r, c) fsm[(s) * (64 * P1LD) + (r) * P1LD + (c)]
#define BS1(s, r, c) fsm[2 * 64 * P1LD + (s) * (128 * P1LD) + (r) * P1LD + (c)]
#define A2(s, r, c)  fsm[(s) * (64 * P2LD) + (r) * P2LD + (c)]
#define B2(s, r, c)  fsm[2 * 64 * P2LD + (s) * (64 * P2LD) + (r) * P2LD + (c)]

__global__ void __launch_bounds__(128)
fc23(const float* __restrict__ C1in,
     const float* __restrict__ w2a, const float* __restrict__ w2b,
     const float* __restrict__ b2a, const float* __restrict__ b2b,
     const float* __restrict__ w3a, const float* __restrict__ w3b,
     const float* __restrict__ b3a, const float* __restrict__ b3b,
     float* __restrict__ H, __half* __restrict__ Hth)
{
    extern __shared__ unsigned fsm[];
    const int tid = threadIdx.x, warp = tid >> 5, lane = tid & 31;
    const int wm = warp & 1, wn = warp >> 1;
    const int gid = lane >> 2, tig = lane & 3;
    const int z = blockIdx.z;
    const size_t m0 = (size_t)blockIdx.x * 64;

    const float* A  = C1in + (size_t)z * 4096 * 256;
    const float* w2 = z ? w2b : w2a;
    const float* b2 = z ? b2b : b2a;
    const float* w3 = z ? w3b : w3a;
    const float* b3 = z ? b3b : b3a;
    float*  Hc  = H   + (size_t)z * 4096 * 64;
    __half* Htc = Hth + (size_t)z * 64 * 4096;

    const int ax = tid & 15, ay = tid >> 4;

    float acc1[2][8][4];
#pragma unroll
    for (int i = 0; i < 2; i++)
#pragma unroll
        for (int j = 0; j < 8; j++)
#pragma unroll
            for (int e = 0; e < 4; e++) acc1[i][j][e] = 0.f;

    for (int k0 = 0; k0 < 256; k0 += 64) {
#pragma unroll
        for (int p = 0; p < 8; p++) {
            int row = p * 8 + ay;
            float4 v = *(const float4*)(A + (m0 + row) * 256 + k0 + ax * 4);
            unsigned h0 = f2t(v.x), h1 = f2t(v.y), h2 = f2t(v.z), h3 = f2t(v.w);
            AS1(0, row, ax * 4 + 0) = h0; AS1(0, row, ax * 4 + 1) = h1;
            AS1(0, row, ax * 4 + 2) = h2; AS1(0, row, ax * 4 + 3) = h3;
            AS1(1, row, ax * 4 + 0) = f2t(v.x - __uint_as_float(h0));
            AS1(1, row, ax * 4 + 1) = f2t(v.y - __uint_as_float(h1));
            AS1(1, row, ax * 4 + 2) = f2t(v.z - __uint_as_float(h2));
            AS1(1, row, ax * 4 + 3) = f2t(v.w - __uint_as_float(h3));
        }
#pragma unroll
        for (int p = 0; p < 16; p++) {
            int row = p * 8 + ay;
            float4 v = *(const float4*)(w2 + (size_t)row * 256 + k0 + ax * 4);
            unsigned h0 = f2t(v.x), h1 = f2t(v.y), h2 = f2t(v.z), h3 = f2t(v.w);
            BS1(0, row, ax * 4 + 0) = h0; BS1(0, row, ax * 4 + 1) = h1;
            BS1(0, row, ax * 4 + 2) = h2; BS1(0, row, ax * 4 + 3) = h3;
            BS1(1, row, ax * 4 + 0) = f2t(v.x - __uint_as_float(h0));
            BS1(1, row, ax * 4 + 1) = f2t(v.y - __uint_as_float(h1));
            BS1(1, row, ax * 4 + 2) = f2t(v.z - __uint_as_float(h2));
            BS1(1, row, ax * 4 + 3) = f2t(v.w - __uint_as_float(h3));
        }
        __syncthreads();

#pragma unroll
        for (int ks = 0; ks < 8; ks++) {
            unsigned af[2][2][4], bf[2][8][2];
#pragma unroll
            for (int s = 0; s < 2; s++) {
#pragma unroll
                for (int mt = 0; mt < 2; mt++) {
                    int rr = wm * 32 + mt * 16 + gid;
                    af[s][mt][0] = AS1(s, rr,     ks * 8 + tig);
                    af[s][mt][1] = AS1(s, rr + 8, ks * 8 + tig);
                    af[s][mt][2] = AS1(s, rr,     ks * 8 + tig + 4);
                    af[s][mt][3] = AS1(s, rr + 8, ks * 8 + tig + 4);
                }
#pragma unroll
                for (int nt = 0; nt < 8; nt++) {
                    int cc = wn * 64 + nt * 8 + gid;
                    bf[s][nt][0] = BS1(s, cc, ks * 8 + tig);
                    bf[s][nt][1] = BS1(s, cc, ks * 8 + tig + 4);
                }
            }
#pragma unroll
            for (int mt = 0; mt < 2; mt++)
#pragma unroll
                for (int nt = 0; nt < 8; nt++) {
                    mma8(acc1[mt][nt], af[0][mt], bf[0][nt]);
                    mma8(acc1[mt][nt], af[0][mt], bf[1][nt]);
                    mma8(acc1[mt][nt], af[1][mt], bf[0][nt]);
                }
        }
        __syncthreads();
    }

#pragma unroll
    for (int mt = 0; mt < 2; mt++)
#pragma unroll
        for (int nt = 0; nt < 8; nt++) {
#pragma unroll
            for (int e = 0; e < 4; e++) {
                int r = wm * 32 + mt * 16 + gid + (e >> 1) * 8;
                int c = wn * 64 + nt * 8 + tig * 2 + (e & 1);
                float v = acc1[mt][nt][e] + b2[c];
                unsigned hi = f2t(v);
                A2(0, r, c) = hi;
                A2(1, r, c) = f2t(v - __uint_as_float(hi));
            }
        }
    {
        const int bx4 = tid & 31, byy = tid >> 5;
#pragma unroll
        for (int p = 0; p < 16; p++) {
            int row = p * 4 + byy;
            float4 v = *(const float4*)(w3 + (size_t)row * 128 + bx4 * 4);
            unsigned h0 = f2t(v.x), h1 = f2t(v.y), h2 = f2t(v.z), h3 = f2t(v.w);
            B2(0, row, bx4 * 4 + 0) = h0; B2(0, row, bx4 * 4 + 1) = h1;
            B2(0, row, bx4 * 4 + 2) = h2; B2(0, row, bx4 * 4 + 3) = h3;
            B2(1, row, bx4 * 4 + 0) = f2t(v.x - __uint_as_float(h0));
            B2(1, row, bx4 * 4 + 1) = f2t(v.y - __uint_as_float(h1));
            B2(1, row, bx4 * 4 + 2) = f2t(v.z - __uint_as_float(h2));
            B2(1, row, bx4 * 4 + 3) = f2t(v.w - __uint_as_float(h3));
        }
    }
    __syncthreads();

    float acc2[2][4][4];
#pragma unroll
    for (int i = 0; i < 2; i++)
#pragma unroll
        for (int j = 0; j < 4; j++)
#pragma unroll
            for (int e = 0; e < 4; e++) acc2[i][j][e] = 0.f;

#pragma unroll
    for (int ks = 0; ks < 16; ks++) {
        unsigned af[2][2][4], bf[2][4][2];
#pragma unroll
        for (int s = 0; s < 2; s++) {
#pragma unroll
            for (int mt = 0; mt < 2; mt++) {
                int rr = wm * 32 + mt * 16 + gid;
                af[s][mt][0] = A2(s, rr,     ks * 8 + tig);
                af[s][mt][1] = A2(s, rr + 8, ks * 8 + tig);
                af[s][mt][2] = A2(s, rr,     ks * 8 + tig + 4);
                af[s][mt][3] = A2(s, rr + 8, ks * 8 + tig + 4);
            }
#pragma unroll
            for (int nt = 0; nt < 4; nt++) {
                int cc = wn * 32 + nt * 8 + gid;
                bf[s][nt][0] = B2(s, cc, ks * 8 + tig);
                bf[s][nt][1] = B2(s, cc, ks * 8 + tig + 4);
            }
        }
#pragma unroll
        for (int mt = 0; mt < 2; mt++)
#pragma unroll
            for (int nt = 0; nt < 4; nt++) {
                mma8(acc2[mt][nt], af[0][mt], bf[0][nt]);
                mma8(acc2[mt][nt], af[0][mt], bf[1][nt]);
                mma8(acc2[mt][nt], af[1][mt], bf[0][nt]);
            }
    }

#pragma unroll
    for (int mt = 0; mt < 2; mt++)
#pragma unroll
        for (int nt = 0; nt < 4; nt++) {
#pragma unroll
            for (int e = 0; e < 4; e++) {
                size_t r = m0 + wm * 32 + mt * 16 + gid + (e >> 1) * 8;
                int c = wn * 32 + nt * 8 + tig * 2 + (e & 1);
                float v = fmaxf(acc2[mt][nt][e] + b3[c], 0.f);
                Hc[r * 64 + c] = v;
                Htc[(size_t)c * 4096 + r] = __float2half_rn(v);
            }
        }
}

// ============================================================================
// Split-K masked aggregation — FP16 HMMA, BK=64; registers cut for 4 CTAs/SM:
// A masked+packed AT LOAD TIME (prefetch = uint2[8], 16 regs); B via cp.async.
// grid (z=2 fastest, m=64, kc=KC).
// ============================================================================
#define LDA 36
__global__ void __launch_bounds__(128, 4)
agg_part_h(const int* __restrict__ adjA, const int* __restrict__ adjB,
           const float* __restrict__ alpha,
           const __half* __restrict__ HtA, const __half* __restrict__ HtB,
           __half* __restrict__ aggp, int* __restrict__ degp, int K)
{
    constexpr int BK = 64;
    extern __shared__ unsigned asm_[];
    unsigned (*Ash)[64][LDA] = (unsigned(*)[64][LDA])asm_;
    unsigned (*Bsh)[64][LDA] = (unsigned(*)[64][LDA])(asm_ + 2 * 64 * LDA);
    int* sdeg = (int*)(asm_ + 4 * 64 * LDA);

    const int tid = threadIdx.x, warp = tid >> 5, lane = tid & 31;
    const int wm = warp & 1, wn = warp >> 1;
    const int gid = lane >> 2, tig = lane & 3;
    const int z = blockIdx.x;
    const int kc = blockIdx.z;
    const int* adj = z ? adjB : adjA;
    const __half* Ht = z ? HtB : HtA;
    const int KCH = K / KC;
    const size_t kbase = (size_t)kc * KCH;
    const size_t m0 = (size_t)blockIdx.y * 64;
    const int ax = tid & 15, ay = tid >> 4;            // A: 16 x 16B/row, 8 rows/pass
    const int bx = tid & 7,  by = tid >> 3;            // B: 8 x 16B/row, 16 rows/pass

    const uint32_t bsm = smem_u32(asm_) + (2 * 64 * LDA) * 4;

    if (tid < 64) sdeg[tid] = 0;

    float acc[2][4][4];
#pragma unroll
    for (int i = 0; i < 2; i++)
#pragma unroll
        for (int j = 0; j < 4; j++)
#pragma unroll
            for (int e = 0; e < 4; e++) acc[i][j][e] = 0.f;

    int cnt[8];
#pragma unroll
    for (int p = 0; p < 8; p++) cnt[p] = 0;

    uint2 rp[8];                                       // packed masked alpha
    const int nIter = KCH / BK;                        // 8

    auto ldA = [&](int it) {                           // load + mask + pack
        const size_t ko = kbase + (size_t)it * BK;
#pragma unroll
        for (int p = 0; p < 8; p++) {
            size_t g = (m0 + p * 8 + ay) * (size_t)K + ko + ax * 4;
            int4 m = *(const int4*)(adj + g);
            float4 v = *(const float4*)(alpha + g);
            int mx = (m.x == 1), my = (m.y == 1), mz = (m.z == 1), mw = (m.w == 1);
            cnt[p] += mx + my + mz + mw;
            rp[p].x = packh2(mx ? v.x : 0.f, my ? v.y : 0.f);
            rp[p].y = packh2(mz ? v.z : 0.f, mw ? v.w : 0.f);
        }
    };
    auto stA = [&](int buf) {
#pragma unroll
        for (int p = 0; p < 8; p++)
            *(uint2*)&Ash[buf][p * 8 + ay][ax * 2] = rp[p];
    };
    auto cpB = [&](int it) {
        const size_t ko = kbase + (size_t)it * BK;
        const int s = it & 1;
#pragma unroll
        for (int p = 0; p < 4; p++) {
            uint32_t dst = bsm + (uint32_t)(s * 64 * LDA + (p * 16 + by) * LDA + bx * 4) * 4;
            cp_async16(dst, Ht + (size_t)(p * 16 + by) * K + ko + bx * 8);
        }
    };

    ldA(0);
    cpB(0); CP_COMMIT();
    stA(0);
    ldA(1);
    CP_WAIT0();
    __syncthreads();

    for (int it = 0; it < nIter; it++) {
        const int cur = it & 1;
        if (it + 1 < nIter) { cpB(it + 1); CP_COMMIT(); stA(cur ^ 1); }
        if (it + 2 < nIter) ldA(it + 2);
#pragma unroll
        for (int ks = 0; ks < BK / 16; ks++) {
            unsigned af[2][4], bf[4][2];
#pragma unroll
            for (int mt = 0; mt < 2; mt++) {
                int rr = wm * 32 + mt * 16 + gid;
                af[mt][0] = Ash[cur][rr    ][ks * 8 + tig];
                af[mt][1] = Ash[cur][rr + 8][ks * 8 + tig];
                af[mt][2] = Ash[cur][rr    ][ks * 8 + tig + 4];
                af[mt][3] = Ash[cur][rr + 8][ks * 8 + tig + 4];
            }
#pragma unroll
            for (int nt = 0; nt < 4; nt++) {
                int cc = wn * 32 + nt * 8 + gid;
                bf[nt][0] = Bsh[cur][cc][ks * 8 + tig];
                bf[nt][1] = Bsh[cur][cc][ks * 8 + tig + 4];
            }
#pragma unroll
            for (int mt = 0; mt < 2; mt++)
#pragma unroll
                for (int nt = 0; nt < 4; nt++)
                    mma16h(acc[mt][nt], af[mt], bf[nt]);
        }
        CP_WAIT0();
        __syncthreads();
    }

#pragma unroll
    for (int p = 0; p < 8; p++) atomicAdd(&sdeg[p * 8 + ay], cnt[p]);
    __syncthreads();

    __half* aout = aggp + ((size_t)z * KC + kc) * 4096 * 64;
    int*    dout = degp + ((size_t)z * KC + kc) * 4096;
    if (tid < 64) dout[m0 + tid] = sdeg[tid];
#pragma unroll
    for (int mt = 0; mt < 2; mt++)
#pragma unroll
        for (int nt = 0; nt < 4; nt++) {
            size_t row = m0 + wm * 32 + mt * 16 + gid;
            size_t col = wn * 32 + nt * 8 + tig * 2;
#pragma unroll
            for (int e = 0; e < 4; e++) {
                size_t r = row + (size_t)(e >> 1) * 8;
                size_t c = col + (size_t)(e & 1);
                aout[r * 64 + c] = __float2half_rn(acc[mt][nt][e]);
            }
        }
}

// ============================================================================
// Classifier stage 1, fused with aggregation finish — WIDE grid; aggp fp16.
// ============================================================================
__global__ void __launch_bounds__(128)
clf_partial(const __half* __restrict__ aggp, const int* __restrict__ degp,
            const float* __restrict__ HA, const float* __restrict__ HB,
            const float* __restrict__ Wp,
            const float* __restrict__ w, float* __restrict__ part)
{
    const int L = 4096 * 64;
    const int TOT = 2 * L;
    const int chunk = 256;
    int base = blockIdx.x * chunk;
    const float W00 = Wp[0];
    float s0 = 0.f, s1 = 0.f;
#pragma unroll
    for (int q = 0; q < 2; q++) {
        int i = base + threadIdx.x + q * 128;
        int z = i >= L;
        int li = i - z * L;
        int r = li >> 6;
        const __half* ap = aggp + (size_t)z * KC * L;
        const int* dp = degp + (size_t)z * KC * 4096;
        float s = 0.f; int d = 0;
#pragma unroll
        for (int kc = 0; kc < KC; kc++) {
            s += __half2float(ap[(size_t)kc * L + li]);
            d += dp[kc * 4096 + r];
        }
        const float* H = z ? HB : HA;
        float v = d ? s * W00 / (float)d + H[li] : 0.f;
        s0 += v * w[i];
        s1 += v * w[TOT + i];
    }
    __shared__ float sm[4][2];
#pragma unroll
    for (int o = 16; o; o >>= 1) {
        s0 += __shfl_down_sync(0xffffffffu, s0, o);
        s1 += __shfl_down_sync(0xffffffffu, s1, o);
    }
    if ((threadIdx.x & 31) == 0) { sm[threadIdx.x >> 5][0] = s0; sm[threadIdx.x >> 5][1] = s1; }
    __syncthreads();
    if (threadIdx.x == 0) {
        float a = 0.f, b = 0.f;
        for (int i = 0; i < 4; i++) { a += sm[i][0]; b += sm[i][1]; }
        part[blockIdx.x * 2 + 0] = a;
        part[blockIdx.x * 2 + 1] = b;
    }
}

__global__ void clf_final(const float* __restrict__ part, const float* __restrict__ bias,
                          float* __restrict__ out, int nb)
{
    float s0 = 0.f, s1 = 0.f;
    for (int i = threadIdx.x; i < nb; i += blockDim.x) { s0 += part[i * 2]; s1 += part[i * 2 + 1]; }
    __shared__ float sm[8][2];
#pragma unroll
    for (int o = 16; o; o >>= 1) {
        s0 += __shfl_down_sync(0xffffffffu, s0, o);
        s1 += __shfl_down_sync(0xffffffffu, s1, o);
    }
    if ((threadIdx.x & 31) == 0) { sm[threadIdx.x >> 5][0] = s0; sm[threadIdx.x >> 5][1] = s1; }
    __syncthreads();
    if (threadIdx.x == 0) {
        float a = 0.f, b = 0.f;
        for (int i = 0; i < (int)(blockDim.x >> 5); i++) { a += sm[i][0]; b += sm[i][1]; }
        out[0] = a + bias[0];
        out[1] = b + bias[1];
    }
}

// ============================================================================
extern "C" void kernel_launch(void* const* d_in, const int* in_sizes, int n_in,
                              void* d_out, int out_size)
{
    const float* x1    = (const float*)d_in[0];
    const float* x2    = (const float*)d_in[1];
    const int*   adj1  = (const int*)d_in[2];
    const int*   adj2  = (const int*)d_in[3];
    const float* e1_w1 = (const float*)d_in[4];
    const float* e1_b1 = (const float*)d_in[5];
    const float* e1_w2 = (const float*)d_in[6];
    const float* e1_b2 = (const float*)d_in[7];
    const float* e1_w3 = (const float*)d_in[8];
    const float* e1_b3 = (const float*)d_in[9];
    const float* e2_w1 = (const float*)d_in[10];
    const float* e2_b1 = (const float*)d_in[11];
    const float* e2_w2 = (const float*)d_in[12];
    const float* e2_b2 = (const float*)d_in[13];
    const float* e2_w3 = (const float*)d_in[14];
    const float* e2_b3 = (const float*)d_in[15];
    const float* W     = (const float*)d_in[16];
    const float* alpha = (const float*)d_in[17];
    const float* clf_w = (const float*)d_in[18];
    const float* clf_b = (const float*)d_in[19];

    float *fc1p, *hp, *partp;
    __half *w1hp, *hthp, *aggpp;
    int *degpp;
    cudaGetSymbolAddress((void**)&fc1p,  g_fc1);
    cudaGetSymbolAddress((void**)&hp,    g_h);
    cudaGetSymbolAddress((void**)&hthp,  g_hth);
    cudaGetSymbolAddress((void**)&partp, g_part);
    cudaGetSymbolAddress((void**)&aggpp, g_aggp);
    cudaGetSymbolAddress((void**)&degpp, g_degp);
    cudaGetSymbolAddress((void**)&w1hp,  g_w1h);

    const int FC1_SMEM  = (2 * 64 * LDH + 2 * 256 * LDH) * 4;           // 92160 B
    const int FC23_SMEM = (2 * 64 * P2LD + 2 * 64 * P2LD) * 4;          // 135168 B
    const int AGG_SMEM  = (4 * 64 * LDA) * 4 + 64 * 4;                  // 37120 B
    cudaFuncSetAttribute(fc1_h, cudaFuncAttributeMaxDynamicSharedMemorySize, FC1_SMEM);
    cudaFuncSetAttribute(fc23,  cudaFuncAttributeMaxDynamicSharedMemorySize, FC23_SMEM);
    cudaFuncSetAttribute(agg_part_h, cudaFuncAttributeMaxDynamicSharedMemorySize, AGG_SMEM);

    // pre-pass: w1 -> RNE fp16
    cvt_w1h<<<2048, 256>>>(e1_w1, e2_w1, w1hp);

    // fc1 (fp16 HMMA, BK=64, BN=256): grid (mt=64, z=2) = 128 CTAs, 2/SM
    fc1_h<<<dim3(64, 2), 256, FC1_SMEM>>>(
        x1, x2, w1hp, e1_b1, e2_b1, fc1p);

    // fused fc2+fc3+relu+transpose: grid (mt=64, 1, z=2) = 128 CTAs
    fc23<<<dim3(64, 1, 2), 128, FC23_SMEM>>>(
        fc1p, e1_w2, e2_w2, e1_b2, e2_b2, e1_w3, e2_w3, e1_b3, e2_b3,
        hp, hthp);

    // split-K masked aggregation (fp16 HMMA, BK=64, 4 CTAs/SM), z fastest
    agg_part_h<<<dim3(2, 64, KC), 128, AGG_SMEM>>>(
        adj1, adj2, alpha, hthp, hthp + 64 * 4096, aggpp, degpp, 4096);

    // classifier stage 1 (fused agg-finish, wide grid) + final
    clf_partial<<<2048, 128>>>(aggpp, degpp, hp, hp + 4096 * 64, W, clf_w, partp);
    clf_final<<<1, 256>>>(partp, clf_b, (float*)d_out, 2048);

    (void)in_sizes; (void)n_in; (void)out_size;
}

// round 17
// speedup vs baseline: 1.0767x; 1.0767x over previous
#include <cuda_runtime.h>
#include <cuda_fp16.h>
#include <cstdint>

#define DI __device__ __forceinline__

DI unsigned f2t(float x) { unsigned u; asm("cvt.rna.tf32.f32 %0, %1;" : "=r"(u) : "f"(x)); return u; }

DI void mma8(float c[4], const unsigned a[4], const unsigned b[2]) {
    asm("mma.sync.aligned.m16n8k8.row.col.f32.tf32.tf32.f32 "
        "{%0,%1,%2,%3}, {%4,%5,%6,%7}, {%8,%9}, {%0,%1,%2,%3};"
        : "+f"(c[0]), "+f"(c[1]), "+f"(c[2]), "+f"(c[3])
        : "r"(a[0]), "r"(a[1]), "r"(a[2]), "r"(a[3]), "r"(b[0]), "r"(b[1]));
}

DI void mma16h(float c[4], const unsigned a[4], const unsigned b[2]) {
    asm("mma.sync.aligned.m16n8k16.row.col.f32.f16.f16.f32 "
        "{%0,%1,%2,%3}, {%4,%5,%6,%7}, {%8,%9}, {%0,%1,%2,%3};"
        : "+f"(c[0]), "+f"(c[1]), "+f"(c[2]), "+f"(c[3])
        : "r"(a[0]), "r"(a[1]), "r"(a[2]), "r"(a[3]), "r"(b[0]), "r"(b[1]));
}

DI unsigned packh2(float lo, float hi) {
    __half2 h = __floats2half2_rn(lo, hi);
    return *(unsigned*)&h;
}

DI uint32_t smem_u32(const void* p) {
    uint32_t a;
    asm("{ .reg .u64 t; cvta.to.shared.u64 t, %1; cvt.u32.u64 %0, t; }" : "=r"(a) : "l"(p));
    return a;
}

DI void cp_async16(uint32_t dst, const void* src) {
    asm volatile("cp.async.ca.shared.global [%0], [%1], 16;" :: "r"(dst), "l"(src) : "memory");
}
#define CP_COMMIT() asm volatile("cp.async.commit_group;" ::: "memory")
#define CP_WAIT0()  asm volatile("cp.async.wait_group 0;" ::: "memory")

// ---- scratch (device globals; no allocations allowed) ----
#define KC 8
__device__ float  g_fc1[2][4096 * 256];
__device__ float  g_h  [2][4096 * 64];
__device__ __half g_hth[2 * 64 * 4096];
__device__ __half g_aggp[2][KC][4096 * 64];
__device__ int    g_degp[2][KC][4096];
__device__ float  g_part[4096];
__device__ __half g_w1h[2 * 256 * 4096];

// ============================================================================
// Pre-pass: w1 -> RNE fp16.
// ============================================================================
__global__ void cvt_w1h(const float* __restrict__ w0, const float* __restrict__ w1,
                        __half* __restrict__ out)
{
    int idx = blockIdx.x * blockDim.x + threadIdx.x;
    int z = idx >= 262144;
    int li = idx - z * 262144;
    float4 v = ((const float4*)(z ? w1 : w0))[li];
    uint2 u;
    u.x = packh2(v.x, v.y);
    u.y = packh2(v.z, v.w);
    ((uint2*)out)[idx] = u;
}

// ============================================================================
// fc1 via FP16 HMMA (R16 config — measured win): BK=64, BM=64 x BN=256;
// B via cp.async (raw halves), 2 CTAs/SM.  grid (mt=64, z=2) = 128 CTAs.
// ============================================================================
#define LDH 36
#define ASH(s, r, c) hsm[(s) * (64 * LDH) + (r) * LDH + (c)]
#define BSH(s, r, c) hsm[2 * 64 * LDH + (s) * (256 * LDH) + (r) * LDH + (c)]

__global__ void __launch_bounds__(256, 2)
fc1_h(const float* __restrict__ A0, const float* __restrict__ A1,
      const __half* __restrict__ Bh,
      const float* __restrict__ bias0, const float* __restrict__ bias1,
      float* __restrict__ C)
{
    extern __shared__ unsigned hsm[];
    constexpr int K = 4096, BK = 64;
    const int tid = threadIdx.x, warp = tid >> 5, lane = tid & 31;
    const int wm = warp & 1, wn = warp >> 1;          // 2 m-warps x 4 n-warps
    const int gid = lane >> 2, tig = lane & 3;
    const int z = blockIdx.y;
    const size_t m0 = (size_t)blockIdx.x * 64;
    const int ax = tid & 15, ay = tid >> 4;           // A: 16 float4/row, 16 rows/pass
    const int bx = tid & 7,  by = tid >> 3;           // B: 8 x 16B/row, 32 rows/pass

    const float*  A = (z ? A1 : A0) + (m0 + ay) * (size_t)K + ax * 4;
    const __half* B = Bh + (size_t)z * 256 * 4096 + (size_t)by * K + bx * 8;
    const float* bias = z ? bias1 : bias0;
    float* Cb = C + (size_t)z * 4096 * 256;

    const uint32_t bsm = smem_u32(hsm) + (2 * 64 * LDH) * 4;

    float acc[2][8][4];
#pragma unroll
    for (int i = 0; i < 2; i++)
#pragma unroll
        for (int j = 0; j < 8; j++)
#pragma unroll
            for (int e = 0; e < 4; e++) acc[i][j][e] = 0.f;

    float4 ra[4];
    const int nIter = K / BK;                          // 64

    auto ldA = [&](int it) {
        const size_t ko = (size_t)it * BK;
#pragma unroll
        for (int p = 0; p < 4; p++)
            ra[p] = *(const float4*)(A + (size_t)p * 16 * K + ko);
    };
    auto stA = [&](int s) {
#pragma unroll
        for (int p = 0; p < 4; p++) {
            uint2 t;
            t.x = packh2(ra[p].x, ra[p].y);
            t.y = packh2(ra[p].z, ra[p].w);
            *(uint2*)&ASH(s, p * 16 + ay, ax * 2) = t;
        }
    };
    auto cpB = [&](int it) {
        const size_t ko = (size_t)it * BK;
        const int s = it & 1;
#pragma unroll
        for (int p = 0; p < 8; p++) {
            uint32_t dst = bsm + (uint32_t)(s * 256 * LDH + (p * 32 + by) * LDH + bx * 4) * 4;
            cp_async16(dst, B + (size_t)p * 32 * K + ko);
        }
    };

    ldA(0);
    cpB(0); CP_COMMIT();
    stA(0);
    ldA(1);
    CP_WAIT0();
    __syncthreads();

    for (int it = 0; it < nIter; it++) {
        const int cur = it & 1;
        if (it + 1 < nIter) { cpB(it + 1); CP_COMMIT(); stA(cur ^ 1); }
        if (it + 2 < nIter) ldA(it + 2);
#pragma unroll
        for (int ks = 0; ks < BK / 16; ks++) {
            unsigned af[2][4], bf[8][2];
#pragma unroll
            for (int mt = 0; mt < 2; mt++) {
                int rr = wm * 32 + mt * 16 + gid;
                af[mt][0] = ASH(cur, rr,     ks * 8 + tig);
                af[mt][1] = ASH(cur, rr + 8, ks * 8 + tig);
                af[mt][2] = ASH(cur, rr,     ks * 8 + tig + 4);
                af[mt][3] = ASH(cur, rr + 8, ks * 8 + tig + 4);
            }
#pragma unroll
            for (int nt = 0; nt < 8; nt++) {
                int cc = wn * 64 + nt * 8 + gid;
                bf[nt][0] = BSH(cur, cc, ks * 8 + tig);
                bf[nt][1] = BSH(cur, cc, ks * 8 + tig + 4);
            }
#pragma unroll
            for (int mt = 0; mt < 2; mt++)
#pragma unroll
                for (int nt = 0; nt < 8; nt++)
                    mma16h(acc[mt][nt], af[mt], bf[nt]);
        }
        CP_WAIT0();
        __syncthreads();
    }

#pragma unroll
    for (int mt = 0; mt < 2; mt++)
#pragma unroll
        for (int nt = 0; nt < 8; nt++) {
            size_t row = m0 + wm * 32 + mt * 16 + gid;
            size_t col = wn * 64 + nt * 8 + tig * 2;
#pragma unroll
            for (int e = 0; e < 4; e++) {
                size_t r = row + (size_t)(e >> 1) * 8;
                size_t c = col + (size_t)(e & 1);
                Cb[r * 256 + c] = acc[mt][nt][e] + bias[c];
            }
        }
}

// ============================================================================
// FUSED fc2+fc3 (+relu, +fp16 transpose) — R14 config, unchanged.
// ============================================================================
#define P1LD 68
#define P2LD 132
#define AS1(s, r, c) fsm[(s) * (64 * P1LD) + (r) * P1LD + (c)]
#define BS1(s, r, c) fsm[2 * 64 * P1LD + (s) * (128 * P1LD) + (r) * P1LD + (c)]
#define A2(s, r, c)  fsm[(s) * (64 * P2LD) + (r) * P2LD + (c)]
#define B2(s, r, c)  fsm[2 * 64 * P2LD + (s) * (64 * P2LD) + (r) * P2LD + (c)]

__global__ void __launch_bounds__(128)
fc23(const float* __restrict__ C1in,
     const float* __restrict__ w2a, const float* __restrict__ w2b,
     const float* __restrict__ b2a, const float* __restrict__ b2b,
     const float* __restrict__ w3a, const float* __restrict__ w3b,
     const float* __restrict__ b3a, const float* __restrict__ b3b,
     float* __restrict__ H, __half* __restrict__ Hth)
{
    extern __shared__ unsigned fsm[];
    const int tid = threadIdx.x, warp = tid >> 5, lane = tid & 31;
    const int wm = warp & 1, wn = warp >> 1;
    const int gid = lane >> 2, tig = lane & 3;
    const int z = blockIdx.z;
    const size_t m0 = (size_t)blockIdx.x * 64;

    const float* A  = C1in + (size_t)z * 4096 * 256;
    const float* w2 = z ? w2b : w2a;
    const float* b2 = z ? b2b : b2a;
    const float* w3 = z ? w3b : w3a;
    const float* b3 = z ? b3b : b3a;
    float*  Hc  = H   + (size_t)z * 4096 * 64;
    __half* Htc = Hth + (size_t)z * 64 * 4096;

    const int ax = tid & 15, ay = tid >> 4;

    float acc1[2][8][4];
#pragma unroll
    for (int i = 0; i < 2; i++)
#pragma unroll
        for (int j = 0; j < 8; j++)
#pragma unroll
            for (int e = 0; e < 4; e++) acc1[i][j][e] = 0.f;

    for (int k0 = 0; k0 < 256; k0 += 64) {
#pragma unroll
        for (int p = 0; p < 8; p++) {
            int row = p * 8 + ay;
            float4 v = *(const float4*)(A + (m0 + row) * 256 + k0 + ax * 4);
            unsigned h0 = f2t(v.x), h1 = f2t(v.y), h2 = f2t(v.z), h3 = f2t(v.w);
            AS1(0, row, ax * 4 + 0) = h0; AS1(0, row, ax * 4 + 1) = h1;
            AS1(0, row, ax * 4 + 2) = h2; AS1(0, row, ax * 4 + 3) = h3;
            AS1(1, row, ax * 4 + 0) = f2t(v.x - __uint_as_float(h0));
            AS1(1, row, ax * 4 + 1) = f2t(v.y - __uint_as_float(h1));
            AS1(1, row, ax * 4 + 2) = f2t(v.z - __uint_as_float(h2));
            AS1(1, row, ax * 4 + 3) = f2t(v.w - __uint_as_float(h3));
        }
#pragma unroll
        for (int p = 0; p < 16; p++) {
            int row = p * 8 + ay;
            float4 v = *(const float4*)(w2 + (size_t)row * 256 + k0 + ax * 4);
            unsigned h0 = f2t(v.x), h1 = f2t(v.y), h2 = f2t(v.z), h3 = f2t(v.w);
            BS1(0, row, ax * 4 + 0) = h0; BS1(0, row, ax * 4 + 1) = h1;
            BS1(0, row, ax * 4 + 2) = h2; BS1(0, row, ax * 4 + 3) = h3;
            BS1(1, row, ax * 4 + 0) = f2t(v.x - __uint_as_float(h0));
            BS1(1, row, ax * 4 + 1) = f2t(v.y - __uint_as_float(h1));
            BS1(1, row, ax * 4 + 2) = f2t(v.z - __uint_as_float(h2));
            BS1(1, row, ax * 4 + 3) = f2t(v.w - __uint_as_float(h3));
        }
        __syncthreads();

#pragma unroll
        for (int ks = 0; ks < 8; ks++) {
            unsigned af[2][2][4], bf[2][8][2];
#pragma unroll
            for (int s = 0; s < 2; s++) {
#pragma unroll
                for (int mt = 0; mt < 2; mt++) {
                    int rr = wm * 32 + mt * 16 + gid;
                    af[s][mt][0] = AS1(s, rr,     ks * 8 + tig);
                    af[s][mt][1] = AS1(s, rr + 8, ks * 8 + tig);
                    af[s][mt][2] = AS1(s, rr,     ks * 8 + tig + 4);
                    af[s][mt][3] = AS1(s, rr + 8, ks * 8 + tig + 4);
                }
#pragma unroll
                for (int nt = 0; nt < 8; nt++) {
                    int cc = wn * 64 + nt * 8 + gid;
                    bf[s][nt][0] = BS1(s, cc, ks * 8 + tig);
                    bf[s][nt][1] = BS1(s, cc, ks * 8 + tig + 4);
                }
            }
#pragma unroll
            for (int mt = 0; mt < 2; mt++)
#pragma unroll
                for (int nt = 0; nt < 8; nt++) {
                    mma8(acc1[mt][nt], af[0][mt], bf[0][nt]);
                    mma8(acc1[mt][nt], af[0][mt], bf[1][nt]);
                    mma8(acc1[mt][nt], af[1][mt], bf[0][nt]);
                }
        }
        __syncthreads();
    }

#pragma unroll
    for (int mt = 0; mt < 2; mt++)
#pragma unroll
        for (int nt = 0; nt < 8; nt++) {
#pragma unroll
            for (int e = 0; e < 4; e++) {
                int r = wm * 32 + mt * 16 + gid + (e >> 1) * 8;
                int c = wn * 64 + nt * 8 + tig * 2 + (e & 1);
                float v = acc1[mt][nt][e] + b2[c];
                unsigned hi = f2t(v);
                A2(0, r, c) = hi;
                A2(1, r, c) = f2t(v - __uint_as_float(hi));
            }
        }
    {
        const int bx4 = tid & 31, byy = tid >> 5;
#pragma unroll
        for (int p = 0; p < 16; p++) {
            int row = p * 4 + byy;
            float4 v = *(const float4*)(w3 + (size_t)row * 128 + bx4 * 4);
            unsigned h0 = f2t(v.x), h1 = f2t(v.y), h2 = f2t(v.z), h3 = f2t(v.w);
            B2(0, row, bx4 * 4 + 0) = h0; B2(0, row, bx4 * 4 + 1) = h1;
            B2(0, row, bx4 * 4 + 2) = h2; B2(0, row, bx4 * 4 + 3) = h3;
            B2(1, row, bx4 * 4 + 0) = f2t(v.x - __uint_as_float(h0));
            B2(1, row, bx4 * 4 + 1) = f2t(v.y - __uint_as_float(h1));
            B2(1, row, bx4 * 4 + 2) = f2t(v.z - __uint_as_float(h2));
            B2(1, row, bx4 * 4 + 3) = f2t(v.w - __uint_as_float(h3));
        }
    }
    __syncthreads();

    float acc2[2][4][4];
#pragma unroll
    for (int i = 0; i < 2; i++)
#pragma unroll
        for (int j = 0; j < 4; j++)
#pragma unroll
            for (int e = 0; e < 4; e++) acc2[i][j][e] = 0.f;

#pragma unroll
    for (int ks = 0; ks < 16; ks++) {
        unsigned af[2][2][4], bf[2][4][2];
#pragma unroll
        for (int s = 0; s < 2; s++) {
#pragma unroll
            for (int mt = 0; mt < 2; mt++) {
                int rr = wm * 32 + mt * 16 + gid;
                af[s][mt][0] = A2(s, rr,     ks * 8 + tig);
                af[s][mt][1] = A2(s, rr + 8, ks * 8 + tig);
                af[s][mt][2] = A2(s, rr,     ks * 8 + tig + 4);
                af[s][mt][3] = A2(s, rr + 8, ks * 8 + tig + 4);
            }
#pragma unroll
            for (int nt = 0; nt < 4; nt++) {
                int cc = wn * 32 + nt * 8 + gid;
                bf[s][nt][0] = B2(s, cc, ks * 8 + tig);
                bf[s][nt][1] = B2(s, cc, ks * 8 + tig + 4);
            }
        }
#pragma unroll
        for (int mt = 0; mt < 2; mt++)
#pragma unroll
            for (int nt = 0; nt < 4; nt++) {
                mma8(acc2[mt][nt], af[0][mt], bf[0][nt]);
                mma8(acc2[mt][nt], af[0][mt], bf[1][nt]);
                mma8(acc2[mt][nt], af[1][mt], bf[0][nt]);
            }
    }

#pragma unroll
    for (int mt = 0; mt < 2; mt++)
#pragma unroll
        for (int nt = 0; nt < 4; nt++) {
#pragma unroll
            for (int e = 0; e < 4; e++) {
                size_t r = m0 + wm * 32 + mt * 16 + gid + (e >> 1) * 8;
                int c = wn * 32 + nt * 8 + tig * 2 + (e & 1);
                float v = fmaxf(acc2[mt][nt][e] + b3[c], 0.f);
                Hc[r * 64 + c] = v;
                Htc[(size_t)c * 4096 + r] = __float2half_rn(v);
            }
        }
}

// ============================================================================
// Split-K masked aggregation — FP16 HMMA, BK=64 (R15 config, best measured:
// LDG register prefetch 2-ahead, fp16 partials, z-fastest grid).
// ============================================================================
#define LDA 36
__global__ void __launch_bounds__(128)
agg_part_h(const int* __restrict__ adjA, const int* __restrict__ adjB,
           const float* __restrict__ alpha,
           const __half* __restrict__ HtA, const __half* __restrict__ HtB,
           __half* __restrict__ aggp, int* __restrict__ degp, int K)
{
    constexpr int BK = 64;
    __shared__ unsigned Ash[2][64][LDA];
    __shared__ unsigned Bsh[2][64][LDA];
    __shared__ int sdeg[64];

    const int tid = threadIdx.x, warp = tid >> 5, lane = tid & 31;
    const int wm = warp & 1, wn = warp >> 1;
    const int gid = lane >> 2, tig = lane & 3;
    const int z = blockIdx.x;                          // fastest (alpha L2 share)
    const int kc = blockIdx.z;
    const int* adj = z ? adjB : adjA;
    const __half* Ht = z ? HtB : HtA;
    const int KCH = K / KC;
    const size_t kbase = (size_t)kc * KCH;
    const size_t m0 = (size_t)blockIdx.y * 64;
    const int ax = tid & 15, ay = tid >> 4;
    const int bx = tid & 7,  by = tid >> 3;

    if (tid < 64) sdeg[tid] = 0;

    float acc[2][4][4];
#pragma unroll
    for (int i = 0; i < 2; i++)
#pragma unroll
        for (int j = 0; j < 4; j++)
#pragma unroll
            for (int e = 0; e < 4; e++) acc[i][j][e] = 0.f;

    int cnt[8];
#pragma unroll
    for (int p = 0; p < 8; p++) cnt[p] = 0;

    int4 rma[8]; float4 rva[8]; uint4 rb[4];
    const int nIter = KCH / BK;

    auto ldA = [&](int it) {
        const size_t ko = kbase + (size_t)it * BK;
#pragma unroll
        for (int p = 0; p < 8; p++) {
            size_t g = (m0 + p * 8 + ay) * (size_t)K + ko + ax * 4;
            rma[p] = *(const int4*)(adj + g);
            rva[p] = *(const float4*)(alpha + g);
        }
#pragma unroll
        for (int p = 0; p < 4; p++)
            rb[p] = *(const uint4*)(Ht + (size_t)(p * 16 + by) * K + ko + bx * 8);
    };
    auto stA = [&](int buf) {
#pragma unroll
        for (int p = 0; p < 8; p++) {
            int row = p * 8 + ay;
            int mx = (rma[p].x == 1), my = (rma[p].y == 1);
            int mz = (rma[p].z == 1), mw = (rma[p].w == 1);
            cnt[p] += mx + my + mz + mw;
            uint2 t;
            t.x = packh2(mx ? rva[p].x : 0.f, my ? rva[p].y : 0.f);
            t.y = packh2(mz ? rva[p].z : 0.f, mw ? rva[p].w : 0.f);
            *(uint2*)&Ash[buf][row][ax * 2] = t;
        }
#pragma unroll
        for (int p = 0; p < 4; p++)
            *(uint4*)&Bsh[buf][p * 16 + by][bx * 4] = rb[p];
    };

    ldA(0); stA(0);
    if (nIter > 1) ldA(1);
    __syncthreads();

    for (int it = 0; it < nIter; it++) {
        const int cur = it & 1;
        if (it + 1 < nIter) stA(cur ^ 1);
        if (it + 2 < nIter) ldA(it + 2);
#pragma unroll
        for (int ks = 0; ks < BK / 16; ks++) {
            unsigned af[2][4], bf[4][2];
#pragma unroll
            for (int mt = 0; mt < 2; mt++) {
                int rr = wm * 32 + mt * 16 + gid;
                af[mt][0] = Ash[cur][rr    ][ks * 8 + tig];
                af[mt][1] = Ash[cur][rr + 8][ks * 8 + tig];
                af[mt][2] = Ash[cur][rr    ][ks * 8 + tig + 4];
                af[mt][3] = Ash[cur][rr + 8][ks * 8 + tig + 4];
            }
#pragma unroll
            for (int nt = 0; nt < 4; nt++) {
                int cc = wn * 32 + nt * 8 + gid;
                bf[nt][0] = Bsh[cur][cc][ks * 8 + tig];
                bf[nt][1] = Bsh[cur][cc][ks * 8 + tig + 4];
            }
#pragma unroll
            for (int mt = 0; mt < 2; mt++)
#pragma unroll
                for (int nt = 0; nt < 4; nt++)
                    mma16h(acc[mt][nt], af[mt], bf[nt]);
        }
        __syncthreads();
    }

#pragma unroll
    for (int p = 0; p < 8; p++) atomicAdd(&sdeg[p * 8 + ay], cnt[p]);
    __syncthreads();

    __half* aout = aggp + ((size_t)z * KC + kc) * 4096 * 64;
    int*    dout = degp + ((size_t)z * KC + kc) * 4096;
    if (tid < 64) dout[m0 + tid] = sdeg[tid];
#pragma unroll
    for (int mt = 0; mt < 2; mt++)
#pragma unroll
        for (int nt = 0; nt < 4; nt++) {
            size_t row = m0 + wm * 32 + mt * 16 + gid;
            size_t col = wn * 32 + nt * 8 + tig * 2;
#pragma unroll
            for (int e = 0; e < 4; e++) {
                size_t r = row + (size_t)(e >> 1) * 8;
                size_t c = col + (size_t)(e & 1);
                aout[r * 64 + c] = __float2half_rn(acc[mt][nt][e]);
            }
        }
}

// ============================================================================
// Classifier stage 1, fused with aggregation finish — WIDE grid; aggp fp16.
// ============================================================================
__global__ void __launch_bounds__(128)
clf_partial(const __half* __restrict__ aggp, const int* __restrict__ degp,
            const float* __restrict__ HA, const float* __restrict__ HB,
            const float* __restrict__ Wp,
            const float* __restrict__ w, float* __restrict__ part)
{
    const int L = 4096 * 64;
    const int TOT = 2 * L;
    const int chunk = 256;
    int base = blockIdx.x * chunk;
    const float W00 = Wp[0];
    float s0 = 0.f, s1 = 0.f;
#pragma unroll
    for (int q = 0; q < 2; q++) {
        int i = base + threadIdx.x + q * 128;
        int z = i >= L;
        int li = i - z * L;
        int r = li >> 6;
        const __half* ap = aggp + (size_t)z * KC * L;
        const int* dp = degp + (size_t)z * KC * 4096;
        float s = 0.f; int d = 0;
#pragma unroll
        for (int kc = 0; kc < KC; kc++) {
            s += __half2float(ap[(size_t)kc * L + li]);
            d += dp[kc * 4096 + r];
        }
        const float* H = z ? HB : HA;
        float v = d ? s * W00 / (float)d + H[li] : 0.f;
        s0 += v * w[i];
        s1 += v * w[TOT + i];
    }
    __shared__ float sm[4][2];
#pragma unroll
    for (int o = 16; o; o >>= 1) {
        s0 += __shfl_down_sync(0xffffffffu, s0, o);
        s1 += __shfl_down_sync(0xffffffffu, s1, o);
    }
    if ((threadIdx.x & 31) == 0) { sm[threadIdx.x >> 5][0] = s0; sm[threadIdx.x >> 5][1] = s1; }
    __syncthreads();
    if (threadIdx.x == 0) {
        float a = 0.f, b = 0.f;
        for (int i = 0; i < 4; i++) { a += sm[i][0]; b += sm[i][1]; }
        part[blockIdx.x * 2 + 0] = a;
        part[blockIdx.x * 2 + 1] = b;
    }
}

__global__ void clf_final(const float* __restrict__ part, const float* __restrict__ bias,
                          float* __restrict__ out, int nb)
{
    float s0 = 0.f, s1 = 0.f;
    for (int i = threadIdx.x; i < nb; i += blockDim.x) { s0 += part[i * 2]; s1 += part[i * 2 + 1]; }
    __shared__ float sm[8][2];
#pragma unroll
    for (int o = 16; o; o >>= 1) {
        s0 += __shfl_down_sync(0xffffffffu, s0, o);
        s1 += __shfl_down_sync(0xffffffffu, s1, o);
    }
    if ((threadIdx.x & 31) == 0) { sm[threadIdx.x >> 5][0] = s0; sm[threadIdx.x >> 5][1] = s1; }
    __syncthreads();
    if (threadIdx.x == 0) {
        float a = 0.f, b = 0.f;
        for (int i = 0; i < (int)(blockDim.x >> 5); i++) { a += sm[i][0]; b += sm[i][1]; }
        out[0] = a + bias[0];
        out[1] = b + bias[1];
    }
}

// ============================================================================
extern "C" void kernel_launch(void* const* d_in, const int* in_sizes, int n_in,
                              void* d_out, int out_size)
{
    const float* x1    = (const float*)d_in[0];
    const float* x2    = (const float*)d_in[1];
    const int*   adj1  = (const int*)d_in[2];
    const int*   adj2  = (const int*)d_in[3];
    const float* e1_w1 = (const float*)d_in[4];
    const float* e1_b1 = (const float*)d_in[5];
    const float* e1_w2 = (const float*)d_in[6];
    const float* e1_b2 = (const float*)d_in[7];
    const float* e1_w3 = (const float*)d_in[8];
    const float* e1_b3 = (const float*)d_in[9];
    const float* e2_w1 = (const float*)d_in[10];
    const float* e2_b1 = (const float*)d_in[11];
    const float* e2_w2 = (const float*)d_in[12];
    const float* e2_b2 = (const float*)d_in[13];
    const float* e2_w3 = (const float*)d_in[14];
    const float* e2_b3 = (const float*)d_in[15];
    const float* W     = (const float*)d_in[16];
    const float* alpha = (const float*)d_in[17];
    const float* clf_w = (const float*)d_in[18];
    const float* clf_b = (const float*)d_in[19];

    float *fc1p, *hp, *partp;
    __half *w1hp, *hthp, *aggpp;
    int *degpp;
    cudaGetSymbolAddress((void**)&fc1p,  g_fc1);
    cudaGetSymbolAddress((void**)&hp,    g_h);
    cudaGetSymbolAddress((void**)&hthp,  g_hth);
    cudaGetSymbolAddress((void**)&partp, g_part);
    cudaGetSymbolAddress((void**)&aggpp, g_aggp);
    cudaGetSymbolAddress((void**)&degpp, g_degp);
    cudaGetSymbolAddress((void**)&w1hp,  g_w1h);

    const int FC1_SMEM  = (2 * 64 * LDH + 2 * 256 * LDH) * 4;           // 92160 B
    const int FC23_SMEM = (2 * 64 * P2LD + 2 * 64 * P2LD) * 4;          // 135168 B
    cudaFuncSetAttribute(fc1_h, cudaFuncAttributeMaxDynamicSharedMemorySize, FC1_SMEM);
    cudaFuncSetAttribute(fc23,  cudaFuncAttributeMaxDynamicSharedMemorySize, FC23_SMEM);

    // pre-pass: w1 -> RNE fp16
    cvt_w1h<<<2048, 256>>>(e1_w1, e2_w1, w1hp);

    // fc1 (fp16 HMMA, BK=64, BN=256, cp.async B, 2 CTAs/SM): 128 CTAs
    fc1_h<<<dim3(64, 2), 256, FC1_SMEM>>>(
        x1, x2, w1hp, e1_b1, e2_b1, fc1p);

    // fused fc2+fc3+relu+transpose: grid (mt=64, 1, z=2) = 128 CTAs
    fc23<<<dim3(64, 1, 2), 128, FC23_SMEM>>>(
        fc1p, e1_w2, e2_w2, e1_b2, e2_b2, e1_w3, e2_w3, e1_b3, e2_b3,
        hp, hthp);

    // split-K masked aggregation (R15 best config), z fastest
    agg_part_h<<<dim3(2, 64, KC), 128>>>(
        adj1, adj2, alpha, hthp, hthp + 64 * 4096, aggpp, degpp, 4096);

    // classifier stage 1 (fused agg-finish, wide grid) + final
    clf_partial<<<2048, 128>>>(aggpp, degpp, hp, hp + 4096 * 64, W, clf_w, partp);
    clf_final<<<1, 256>>>(partp, clf_b, (float*)d_out, 2048);

    (void)in_sizes; (void)n_in; (void)out_size;
}